// round 2
// baseline (speedup 1.0000x reference)
#include <cuda_runtime.h>

#define FULLMASK 0xFFFFFFFFu

#define HID   64
#define G4    256        // 4*HID gates
#define RS    8          // receptive window
#define KIH   24         // 3*RS input features
#define WIDTH 24
#define L0R   8
#define R0R   24
#define OW    16
#define WB    8          // batch elements per warp
#define NWARP 4
#define CTAB  (WB*NWARP) // 32 batch per CTA

// shared-memory float offsets
#define OFF_WIH  0
#define OFF_WHH  (KIH*G4)                    // 6144
#define OFF_BIAS (OFF_WHH + HID*G4)          // 22528
#define OFF_WL   (OFF_BIAS + G4)             // 22784
#define OFF_BL   (OFF_WL + 3*HID)            // 22976
#define OFF_RB   (OFF_BL + 4)                // 22980
#define SMEM_FLOATS (OFF_RB + CTAB*3*WIDTH)  // 25284 -> ~101 KB

static __device__ __forceinline__ float sigf(float x){
  return __fdividef(1.0f, 1.0f + __expf(-x));
}
static __device__ __forceinline__ float tanhf_fast(float x){
  return __fdividef(2.0f, 1.0f + __expf(-2.0f*x)) - 1.0f;
}

__global__ void __launch_bounds__(128)
pixelrnn_kernel(const float* __restrict__ x,
                const float* __restrict__ W_ih,
                const float* __restrict__ W_hh,
                const float* __restrict__ b_ih,
                const float* __restrict__ b_hh,
                const float* __restrict__ Wl,
                const float* __restrict__ bl,
                float* __restrict__ out)
{
  extern __shared__ float sm[];
  const int tid = threadIdx.x;

  // Stage weights transposed: sm_w[k][g] = W[g][k] so lanes read g-contiguous.
  for (int i = tid; i < KIH*G4; i += 128){
    int k = i >> 8, g = i & 255;
    sm[OFF_WIH + i] = W_ih[g*KIH + k];
  }
  for (int i = tid; i < HID*G4; i += 128){
    int k = i >> 8, g = i & 255;
    sm[OFF_WHH + i] = W_hh[g*HID + k];
  }
  for (int i = tid; i < G4; i += 128) sm[OFF_BIAS + i] = b_ih[i] + b_hh[i];
  for (int i = tid; i < 3*HID; i += 128) sm[OFF_WL + i] = Wl[i];
  if (tid < 3) sm[OFF_BL + tid] = bl[tid];
  __syncthreads();

  const int warp = tid >> 5, lane = tid & 31;
  const int bbase = blockIdx.x * CTAB + warp * WB;
  float* rb = sm + OFF_RB + warp * (WB*3*WIDTH);   // per-warp row buffer

  // State: lane holds gate/hidden index `lane` (suffix 0) and `lane+32`
  // (suffix 1) for each of the WB batch elements.
  float hx0[WB], hx1[WB], cx0[WB], cx1[WB];
#pragma unroll
  for (int b = 0; b < WB; b++){ hx0[b]=0.f; hx1[b]=0.f; cx0[b]=0.f; cx1[b]=0.f; }

  float bj[8];
#pragma unroll
  for (int j = 0; j < 8; j++) bj[j] = sm[OFF_BIAS + lane + 32*j];
  float wl0[3], wl1[3], blv[3];
#pragma unroll
  for (int ch = 0; ch < 3; ch++){
    wl0[ch] = sm[OFF_WL + ch*HID + lane];
    wl1[ch] = sm[OFF_WL + ch*HID + lane + 32];
    blv[ch] = sm[OFF_BL + ch];
  }

  for (int r = L0R; r < R0R; r++){
    // Fresh row buffer from x for this row (hx/cx persist across rows).
    for (int i = lane; i < WB*3*WIDTH; i += 32){
      int b   = i / (3*WIDTH);
      int rem = i - b*(3*WIDTH);
      int ch  = rem / WIDTH;
      int col = rem - ch*WIDTH;
      rb[i] = x[(size_t)(bbase+b)*(3*WIDTH*WIDTH) + ch*(WIDTH*WIDTH) + r*WIDTH + col];
    }
    __syncwarp();

    for (int c = RS; c < WIDTH; c++){
      // gates acc[b][j] corresponds to gate index (lane + 32*j):
      // j=0,1 -> i ; j=2,3 -> f ; j=4,5 -> g ; j=6,7 -> o
      float acc[WB][8];
#pragma unroll
      for (int b = 0; b < WB; b++)
#pragma unroll
        for (int j = 0; j < 8; j++) acc[b][j] = bj[j];

      // ---- input contribution: feed[k], k = ch*8 + pos, col = c-8+pos ----
      const float* wbase = sm + OFF_WIH + lane;
#pragma unroll 2
      for (int k = 0; k < KIH; k++){
        int kc = k >> 3, kp = k & 7;
        float w[8];
#pragma unroll
        for (int j = 0; j < 8; j++) w[j] = wbase[k*G4 + 32*j];
#pragma unroll
        for (int b = 0; b < WB; b++){
          float a = rb[b*(3*WIDTH) + kc*WIDTH + (c - RS + kp)];
#pragma unroll
          for (int j = 0; j < 8; j++) acc[b][j] = fmaf(a, w[j], acc[b][j]);
        }
      }

      // ---- hidden contribution: broadcast hx[k] via shuffle ----
      const float* hbase = sm + OFF_WHH + lane;
#pragma unroll 2
      for (int k = 0; k < 32; k++){
        float w[8];
#pragma unroll
        for (int j = 0; j < 8; j++) w[j] = hbase[k*G4 + 32*j];
#pragma unroll
        for (int b = 0; b < WB; b++){
          float h = __shfl_sync(FULLMASK, hx0[b], k);
#pragma unroll
          for (int j = 0; j < 8; j++) acc[b][j] = fmaf(h, w[j], acc[b][j]);
        }
      }
#pragma unroll 2
      for (int k = 0; k < 32; k++){
        float w[8];
#pragma unroll
        for (int j = 0; j < 8; j++) w[j] = hbase[(k+32)*G4 + 32*j];
#pragma unroll
        for (int b = 0; b < WB; b++){
          float h = __shfl_sync(FULLMASK, hx1[b], k);
#pragma unroll
          for (int j = 0; j < 8; j++) acc[b][j] = fmaf(h, w[j], acc[b][j]);
        }
      }

      // ---- LSTM cell update + head partials ----
      float p[WB][3];
#pragma unroll
      for (int b = 0; b < WB; b++){
        float c0 = sigf(acc[b][2])*cx0[b] + sigf(acc[b][0])*tanhf_fast(acc[b][4]);
        float c1 = sigf(acc[b][3])*cx1[b] + sigf(acc[b][1])*tanhf_fast(acc[b][5]);
        cx0[b] = c0; cx1[b] = c1;
        float h0 = sigf(acc[b][6])*tanhf_fast(c0);
        float h1 = sigf(acc[b][7])*tanhf_fast(c1);
        hx0[b] = h0; hx1[b] = h1;
#pragma unroll
        for (int ch = 0; ch < 3; ch++)
          p[b][ch] = h0*wl0[ch] + h1*wl1[ch];
      }

      // butterfly-reduce the 24 head dot-products across the warp
#pragma unroll
      for (int off = 16; off >= 1; off >>= 1)
#pragma unroll
        for (int b = 0; b < WB; b++)
#pragma unroll
          for (int ch = 0; ch < 3; ch++)
            p[b][ch] += __shfl_xor_sync(FULLMASK, p[b][ch], off);

      // leaky-relu, write back into rowbuf (autoregressive feed) and to output
#pragma unroll
      for (int b = 0; b < WB; b++)
#pragma unroll
        for (int ch = 0; ch < 3; ch++){
          float v = p[b][ch] + blv[ch];
          v = (v >= 0.f) ? v : 0.01f*v;
          if (lane == b*3 + ch){
            rb[b*(3*WIDTH) + ch*WIDTH + c] = v;
            out[((size_t)(bbase+b)*3 + ch)*(OW*OW) + (r - L0R)*OW + (c - RS)] = v;
          }
        }
      __syncwarp();
    }
  }
}

extern "C" void kernel_launch(void* const* d_in, const int* in_sizes, int n_in,
                              void* d_out, int out_size)
{
  const float* x    = (const float*)d_in[0];
  const float* W_ih = (const float*)d_in[1];
  const float* W_hh = (const float*)d_in[2];
  const float* b_ih = (const float*)d_in[3];
  const float* b_hh = (const float*)d_in[4];
  const float* Wl   = (const float*)d_in[5];
  const float* bl   = (const float*)d_in[6];

  int B = in_sizes[0] / (3*WIDTH*WIDTH);
  int grid = B / CTAB;   // 4096/32 = 128 CTAs

  size_t smem = SMEM_FLOATS * sizeof(float);   // ~101 KB
  cudaFuncSetAttribute(pixelrnn_kernel,
                       cudaFuncAttributeMaxDynamicSharedMemorySize, (int)smem);

  pixelrnn_kernel<<<grid, 128, smem>>>(x, W_ih, W_hh, b_ih, b_hh, Wl, bl,
                                       (float*)d_out);
}

// round 3
// speedup vs baseline: 1.1167x; 1.1167x over previous
#include <cuda_runtime.h>

#define FULLMASK 0xFFFFFFFFu

#define HID   64
#define G4    256        // 4*HID gates
#define RS    8          // receptive window
#define KIH   24         // 3*RS input features
#define WIDTH 24
#define L0R   8
#define R0R   24
#define OW    16
#define WB    4          // batch elements per warp
#define NWARP 8
#define NTHR  (NWARP*32)
#define CTAB  (WB*NWARP) // 32 batch per CTA

// shared-memory float offsets (weights stored as float2 gate-pairs)
#define OFF_WIH  0                           // KIH*128 float2 = 6144 floats
#define OFF_WHH  (KIH*G4)                    // 6144: HID*128 float2 = 16384 floats
#define OFF_BIAS (OFF_WHH + HID*G4)          // 22528
#define OFF_WL   (OFF_BIAS + G4)             // 22784
#define OFF_BL   (OFF_WL + 3*HID)            // 22976
#define OFF_RB   (OFF_BL + 4)                // 22980
#define SMEM_FLOATS (OFF_RB + NWARP*WB*3*WIDTH)  // 25284 -> ~101 KB

typedef unsigned long long u64;

static __device__ __forceinline__ u64 pack2(float a, float b){
  u64 r; asm("mov.b64 %0, {%1, %2};" : "=l"(r) : "f"(a), "f"(b)); return r;
}
static __device__ __forceinline__ void unpack2(u64 v, float& a, float& b){
  asm("mov.b64 {%0, %1}, %2;" : "=f"(a), "=f"(b) : "l"(v));
}
static __device__ __forceinline__ u64 ffma2(u64 a, u64 b, u64 c){
  u64 d; asm("fma.rn.f32x2 %0, %1, %2, %3;" : "=l"(d) : "l"(a), "l"(b), "l"(c));
  return d;
}

static __device__ __forceinline__ float sigf(float x){
  return __fdividef(1.0f, 1.0f + __expf(-x));
}
static __device__ __forceinline__ float tanhf_fast(float x){
  return __fdividef(2.0f, 1.0f + __expf(-2.0f*x)) - 1.0f;
}

__global__ void __launch_bounds__(NTHR)
pixelrnn_kernel(const float* __restrict__ x,
                const float* __restrict__ W_ih,
                const float* __restrict__ W_hh,
                const float* __restrict__ b_ih,
                const float* __restrict__ b_hh,
                const float* __restrict__ Wl,
                const float* __restrict__ bl,
                float* __restrict__ out)
{
  extern __shared__ float sm[];
  const int tid = threadIdx.x;

  // Stage weights as float2 gate-pairs:
  //   pair t (t=0..3) of lane ln holds gates (ln+64t, ln+64t+32)
  //   -> one LDS.64 feeds one fma.rn.f32x2
  float2* wih2 = (float2*)(sm + OFF_WIH);
  for (int i = tid; i < KIH*128; i += NTHR){
    int k = i >> 7, idx = i & 127, t = idx >> 5, ln = idx & 31;
    int g0 = ln + 64*t;
    wih2[i] = make_float2(W_ih[g0*KIH + k], W_ih[(g0+32)*KIH + k]);
  }
  float2* whh2 = (float2*)(sm + OFF_WHH);
  for (int i = tid; i < HID*128; i += NTHR){
    int k = i >> 7, idx = i & 127, t = idx >> 5, ln = idx & 31;
    int g0 = ln + 64*t;
    whh2[i] = make_float2(W_hh[g0*HID + k], W_hh[(g0+32)*HID + k]);
  }
  for (int i = tid; i < G4; i += NTHR) sm[OFF_BIAS + i] = b_ih[i] + b_hh[i];
  for (int i = tid; i < 3*HID; i += NTHR) sm[OFF_WL + i] = Wl[i];
  if (tid < 3) sm[OFF_BL + tid] = bl[tid];
  __syncthreads();

  const int warp = tid >> 5, lane = tid & 31;
  const int bbase = blockIdx.x * CTAB + warp * WB;
  float* rb = sm + OFF_RB + warp * (WB*3*WIDTH);   // per-warp row buffer

  const u64* wihu = (const u64*)(sm + OFF_WIH) + lane;
  const u64* whhu = (const u64*)(sm + OFF_WHH) + lane;

  // State: lane holds hidden index `lane` (suffix 0) and `lane+32` (suffix 1).
  float hx0[WB], hx1[WB], cx0[WB], cx1[WB];
#pragma unroll
  for (int b = 0; b < WB; b++){ hx0[b]=0.f; hx1[b]=0.f; cx0[b]=0.f; cx1[b]=0.f; }

  u64 bj2[4];
#pragma unroll
  for (int t = 0; t < 4; t++)
    bj2[t] = pack2(sm[OFF_BIAS + lane + 64*t], sm[OFF_BIAS + lane + 64*t + 32]);

  float wl0[3], wl1[3], blv[3];
#pragma unroll
  for (int ch = 0; ch < 3; ch++){
    wl0[ch] = sm[OFF_WL + ch*HID + lane];
    wl1[ch] = sm[OFF_WL + ch*HID + lane + 32];
    blv[ch] = sm[OFF_BL + ch];
  }

  for (int r = L0R; r < R0R; r++){
    // Fresh row buffer from x for this row (hx/cx persist across rows).
    for (int i = lane; i < WB*3*WIDTH; i += 32){
      int b   = i / (3*WIDTH);
      int rem = i - b*(3*WIDTH);
      int ch  = rem / WIDTH;
      int col = rem - ch*WIDTH;
      rb[i] = x[(size_t)(bbase+b)*(3*WIDTH*WIDTH) + ch*(WIDTH*WIDTH) + r*WIDTH + col];
    }
    __syncwarp();

    for (int c = RS; c < WIDTH; c++){
      // acc[b][t] packs gates (lane+64t, lane+64t+32):
      // t=0 -> i ; t=1 -> f ; t=2 -> g ; t=3 -> o
      u64 acc[WB][4];
#pragma unroll
      for (int b = 0; b < WB; b++)
#pragma unroll
        for (int t = 0; t < 4; t++) acc[b][t] = bj2[t];

      // ---- input contribution ----
#pragma unroll 2
      for (int k = 0; k < KIH; k++){
        int kc = k >> 3, kp = k & 7;
        u64 w[4];
#pragma unroll
        for (int t = 0; t < 4; t++) w[t] = wihu[k*128 + 32*t];
#pragma unroll
        for (int b = 0; b < WB; b++){
          float a = rb[b*(3*WIDTH) + kc*WIDTH + (c - RS + kp)];
          u64 aa = pack2(a, a);
#pragma unroll
          for (int t = 0; t < 4; t++) acc[b][t] = ffma2(aa, w[t], acc[b][t]);
        }
      }

      // ---- hidden contribution: broadcast hx[k] via shuffle ----
#pragma unroll 2
      for (int k = 0; k < 32; k++){
        u64 w[4];
#pragma unroll
        for (int t = 0; t < 4; t++) w[t] = whhu[k*128 + 32*t];
#pragma unroll
        for (int b = 0; b < WB; b++){
          float h = __shfl_sync(FULLMASK, hx0[b], k);
          u64 hh = pack2(h, h);
#pragma unroll
          for (int t = 0; t < 4; t++) acc[b][t] = ffma2(hh, w[t], acc[b][t]);
        }
      }
#pragma unroll 2
      for (int k = 0; k < 32; k++){
        u64 w[4];
#pragma unroll
        for (int t = 0; t < 4; t++) w[t] = whhu[(k+32)*128 + 32*t];
#pragma unroll
        for (int b = 0; b < WB; b++){
          float h = __shfl_sync(FULLMASK, hx1[b], k);
          u64 hh = pack2(h, h);
#pragma unroll
          for (int t = 0; t < 4; t++) acc[b][t] = ffma2(hh, w[t], acc[b][t]);
        }
      }

      // ---- LSTM cell update + head partials ----
      float p[WB][3];
#pragma unroll
      for (int b = 0; b < WB; b++){
        float i0,i1,f0,f1,g0,g1,o0,o1;
        unpack2(acc[b][0], i0, i1);
        unpack2(acc[b][1], f0, f1);
        unpack2(acc[b][2], g0, g1);
        unpack2(acc[b][3], o0, o1);
        float c0 = sigf(f0)*cx0[b] + sigf(i0)*tanhf_fast(g0);
        float c1 = sigf(f1)*cx1[b] + sigf(i1)*tanhf_fast(g1);
        cx0[b] = c0; cx1[b] = c1;
        float h0 = sigf(o0)*tanhf_fast(c0);
        float h1 = sigf(o1)*tanhf_fast(c1);
        hx0[b] = h0; hx1[b] = h1;
#pragma unroll
        for (int ch = 0; ch < 3; ch++)
          p[b][ch] = h0*wl0[ch] + h1*wl1[ch];
      }

      // butterfly-reduce the 12 head dot-products across the warp
#pragma unroll
      for (int off = 16; off >= 1; off >>= 1)
#pragma unroll
        for (int b = 0; b < WB; b++)
#pragma unroll
          for (int ch = 0; ch < 3; ch++)
            p[b][ch] += __shfl_xor_sync(FULLMASK, p[b][ch], off);

      // leaky-relu, write back into rowbuf (autoregressive feed) and to output
#pragma unroll
      for (int b = 0; b < WB; b++)
#pragma unroll
        for (int ch = 0; ch < 3; ch++){
          float v = p[b][ch] + blv[ch];
          v = (v >= 0.f) ? v : 0.01f*v;
          if (lane == b*3 + ch){
            rb[b*(3*WIDTH) + ch*WIDTH + c] = v;
            out[((size_t)(bbase+b)*3 + ch)*(OW*OW) + (r - L0R)*OW + (c - RS)] = v;
          }
        }
      __syncwarp();
    }
  }
}

extern "C" void kernel_launch(void* const* d_in, const int* in_sizes, int n_in,
                              void* d_out, int out_size)
{
  const float* x    = (const float*)d_in[0];
  const float* W_ih = (const float*)d_in[1];
  const float* W_hh = (const float*)d_in[2];
  const float* b_ih = (const float*)d_in[3];
  const float* b_hh = (const float*)d_in[4];
  const float* Wl   = (const float*)d_in[5];
  const float* bl   = (const float*)d_in[6];

  int B = in_sizes[0] / (3*WIDTH*WIDTH);
  int grid = B / CTAB;   // 4096/32 = 128 CTAs

  size_t smem = SMEM_FLOATS * sizeof(float);   // ~101 KB
  cudaFuncSetAttribute(pixelrnn_kernel,
                       cudaFuncAttributeMaxDynamicSharedMemorySize, (int)smem);

  pixelrnn_kernel<<<grid, NTHR, smem>>>(x, W_ih, W_hh, b_ih, b_hh, Wl, bl,
                                        (float*)d_out);
}

// round 4
// speedup vs baseline: 1.3269x; 1.1883x over previous
#include <cuda_runtime.h>

#define FULLMASK 0xFFFFFFFFu

#define HID   64
#define G4    256
#define RS    8
#define KIH   24
#define WIDTH 24
#define L0R   8
#define R0R   24
#define OW    16
#define PB    8          // batches per warp-pair
#define NWARP 8          // 4 pairs
#define NTHR  256
#define CTAB  32

#define KQ_IN  6         // input k-quads  (k = (q>>1)*8 + (q&1)*4 + ...)
#define KQ_HID 16        // hidden k-quads (k = 4q)
#define KQTOT  22

// smem float offsets
#define OFF_W    0
#define W_FLOATS (2*KQTOT*4*32*4)            // 22528
#define OFF_BIAS (OFF_W + W_FLOATS)          // 22528
#define OFF_WL   (OFF_BIAS + G4)             // 22784
#define OFF_BL   (OFF_WL + 3*HID)            // 22976
#define OFF_HX   (OFF_BL + 4)                // 22980
#define HX_FLOATS (4*PB*HID)                 // 2048
#define OFF_XCH  (OFF_HX + HX_FLOATS)        // 25028
#define XCH_FLOATS (4*PB*2*32*4)             // 8192
#define OFF_RBQ  (OFF_XCH + XCH_FLOATS)      // 33220
#define RBQ_FLOATS (4*PB*3*WIDTH*4)          // 9216
#define SMEM_FLOATS (OFF_RBQ + RBQ_FLOATS)   // 42436 -> ~166 KB

typedef unsigned long long u64;

union F4U { float4 f4; struct { u64 lo, hi; } u; };

static __device__ __forceinline__ u64 pack2(float a, float b){
  u64 r; asm("mov.b64 %0, {%1, %2};" : "=l"(r) : "f"(a), "f"(b)); return r;
}
static __device__ __forceinline__ void unpack2(u64 v, float& a, float& b){
  asm("mov.b64 {%0, %1}, %2;" : "=f"(a), "=f"(b) : "l"(v));
}
static __device__ __forceinline__ u64 ffma2(u64 a, u64 b, u64 c){
  u64 d; asm("fma.rn.f32x2 %0, %1, %2, %3;" : "=l"(d) : "l"(a), "l"(b), "l"(c));
  return d;
}
static __device__ __forceinline__ float sigf(float x){
  return __fdividef(1.0f, 1.0f + __expf(-x));
}
static __device__ __forceinline__ float tanhf_fast(float x){
  return __fdividef(2.0f, 1.0f + __expf(-2.0f*x)) - 1.0f;
}

#define PBAR() asm volatile("bar.sync %0, 64;" :: "r"(pair + 1) : "memory")

__global__ void __launch_bounds__(NTHR, 1)
pixelrnn_kernel(const float* __restrict__ x,
                const float* __restrict__ W_ih,
                const float* __restrict__ W_hh,
                const float* __restrict__ b_ih,
                const float* __restrict__ b_hh,
                const float* __restrict__ Wl,
                const float* __restrict__ bl,
                float* __restrict__ out)
{
  extern __shared__ float sm[];
  const int tid  = threadIdx.x;
  const int warp = tid >> 5, lane = tid & 31;
  const int pair = warp >> 1, half = warp & 1;

  // ---- stage weights: u128 idx = ((h*22 + q)*4 + s)*32 + ln, s = p*2 + t ----
  // float4 = ( w(k,g0), w(k+1,g0), w(k,g1), w(k+1,g1) )
  //   k  = 4q + 2p (input, q<6)  or  4(q-6) + 2p (hidden)
  //   g0 = ln + 64t + 128h, g1 = g0 + 32
  {
    float4* Wq = (float4*)(sm + OFF_W);
    for (int i = tid; i < 2*KQTOT*4*32; i += NTHR){
      int ln = i & 31;
      int s  = (i >> 5) & 3;
      int hq = i >> 7;
      int q  = hq % KQTOT;
      int h  = hq / KQTOT;
      int t = s & 1, p = s >> 1;
      int g0 = ln + 64*t + 128*h;
      int g1 = g0 + 32;
      float4 v;
      if (q < KQ_IN){
        int kk = 4*q + 2*p;
        v = make_float4(W_ih[g0*KIH + kk], W_ih[g0*KIH + kk + 1],
                        W_ih[g1*KIH + kk], W_ih[g1*KIH + kk + 1]);
      } else {
        int kk = 4*(q - KQ_IN) + 2*p;
        v = make_float4(W_hh[g0*HID + kk], W_hh[g0*HID + kk + 1],
                        W_hh[g1*HID + kk], W_hh[g1*HID + kk + 1]);
      }
      Wq[i] = v;
    }
  }
  for (int i = tid; i < G4; i += NTHR) sm[OFF_BIAS + i] = b_ih[i] + b_hh[i];
  for (int i = tid; i < 3*HID; i += NTHR) sm[OFF_WL + i] = Wl[i];
  if (tid < 3) sm[OFF_BL + tid] = bl[tid];
  for (int i = tid; i < HX_FLOATS; i += NTHR) sm[OFF_HX + i] = 0.f;   // h0 = 0
  __syncthreads();

  const int bpair = blockIdx.x * CTAB + pair * PB;
  float*  hxs = sm + OFF_HX + pair * (PB*HID);
  float4* xch = (float4*)(sm + OFF_XCH) + pair * (PB*2*32);
  float4* rbq = (float4*)(sm + OFF_RBQ) + pair * (PB*3*WIDTH);
  float*  rbf = (float*)rbq;
  const float4* wbase = (const float4*)(sm + OFF_W) + half*(KQTOT*4*32) + lane;

  float bj[4];
#pragma unroll
  for (int jj = 0; jj < 4; jj++) bj[jj] = sm[OFF_BIAS + lane + 32*jj + 128*half];

  const int bown = half * 4;          // local owned batches bown..bown+3
  const int bexp = 4 - bown;          // exported batches
  float cx0[4], cx1[4];
#pragma unroll
  for (int b = 0; b < 4; b++){ cx0[b] = 0.f; cx1[b] = 0.f; }

  float wl0[3], wl1[3], blv[3];
#pragma unroll
  for (int ch = 0; ch < 3; ch++){
    wl0[ch] = sm[OFF_WL + ch*HID + lane];
    wl1[ch] = sm[OFF_WL + ch*HID + lane + 32];
    blv[ch] = sm[OFF_BL + ch];
  }

  for (int r = L0R; r < R0R; r++){
    // row buffer init from x: rbq[(b*3+ch)*24 + base] = (v[base..base+3])
    for (int i = lane + 32*half; i < PB*3*WIDTH; i += 64){
      int b = i / (3*WIDTH);
      int rem = i - b*(3*WIDTH);
      int ch = rem / WIDTH;
      int base = rem - ch*WIDTH;
      const float* xr = x + (size_t)(bpair + b)*(3*WIDTH*WIDTH)
                          + ch*(WIDTH*WIDTH) + r*WIDTH;
      float v0 = xr[base];
      float v1 = (base+1 < WIDTH) ? xr[base+1] : 0.f;
      float v2 = (base+2 < WIDTH) ? xr[base+2] : 0.f;
      float v3 = (base+3 < WIDTH) ? xr[base+3] : 0.f;
      rbq[i] = make_float4(v0, v1, v2, v3);
    }
    PBAR();

    for (int c = RS; c < WIDTH; c++){
      // acc[b][jj]: u64 = (even-k partial, odd-k partial) for gate ln+32jj+128h
      u64 acc[PB][4];
#pragma unroll
      for (int b = 0; b < PB; b++)
#pragma unroll
        for (int jj = 0; jj < 4; jj++) acc[b][jj] = pack2(bj[jj], 0.f);

      // ---- input k-quads ----
#pragma unroll
      for (int q = 0; q < KQ_IN; q++){
        F4U w0, w1, w2, w3;
        w0.f4 = wbase[(q*4 + 0)*32];
        w1.f4 = wbase[(q*4 + 1)*32];
        w2.f4 = wbase[(q*4 + 2)*32];
        w3.f4 = wbase[(q*4 + 3)*32];
        int ch = q >> 1, qi = q & 1;
        int base = c - RS + 4*qi;
#pragma unroll
        for (int b = 0; b < PB; b++){
          F4U a; a.f4 = rbq[(b*3 + ch)*WIDTH + base];
          acc[b][0] = ffma2(a.u.lo, w0.u.lo, acc[b][0]);
          acc[b][1] = ffma2(a.u.lo, w0.u.hi, acc[b][1]);
          acc[b][2] = ffma2(a.u.lo, w1.u.lo, acc[b][2]);
          acc[b][3] = ffma2(a.u.lo, w1.u.hi, acc[b][3]);
          acc[b][0] = ffma2(a.u.hi, w2.u.lo, acc[b][0]);
          acc[b][1] = ffma2(a.u.hi, w2.u.hi, acc[b][1]);
          acc[b][2] = ffma2(a.u.hi, w3.u.lo, acc[b][2]);
          acc[b][3] = ffma2(a.u.hi, w3.u.hi, acc[b][3]);
        }
      }

      // ---- hidden k-quads ----
#pragma unroll 4
      for (int q = 0; q < KQ_HID; q++){
        F4U w0, w1, w2, w3;
        w0.f4 = wbase[((KQ_IN + q)*4 + 0)*32];
        w1.f4 = wbase[((KQ_IN + q)*4 + 1)*32];
        w2.f4 = wbase[((KQ_IN + q)*4 + 2)*32];
        w3.f4 = wbase[((KQ_IN + q)*4 + 3)*32];
#pragma unroll
        for (int b = 0; b < PB; b++){
          F4U a; a.f4 = *(const float4*)&hxs[b*HID + 4*q];
          acc[b][0] = ffma2(a.u.lo, w0.u.lo, acc[b][0]);
          acc[b][1] = ffma2(a.u.lo, w0.u.hi, acc[b][1]);
          acc[b][2] = ffma2(a.u.lo, w1.u.lo, acc[b][2]);
          acc[b][3] = ffma2(a.u.lo, w1.u.hi, acc[b][3]);
          acc[b][0] = ffma2(a.u.hi, w2.u.lo, acc[b][0]);
          acc[b][1] = ffma2(a.u.hi, w2.u.hi, acc[b][1]);
          acc[b][2] = ffma2(a.u.hi, w3.u.lo, acc[b][2]);
          acc[b][3] = ffma2(a.u.hi, w3.u.hi, acc[b][3]);
        }
      }

      // ---- finalize gates (even + odd streams) ----
      float gf[PB][4];
#pragma unroll
      for (int b = 0; b < PB; b++)
#pragma unroll
        for (int jj = 0; jj < 4; jj++){
          float lo, hi; unpack2(acc[b][jj], lo, hi);
          gf[b][jj] = lo + hi;
        }

      // ---- export own-half gates for the other warp's batches ----
#pragma unroll
      for (int bb = 0; bb < 4; bb++){
        int b = bexp + bb;
        xch[(b*2 + half)*32 + lane] =
            make_float4(gf[b][0], gf[b][1], gf[b][2], gf[b][3]);
      }
      PBAR();

      // ---- cell update for owned batches ----
      float p[4][3];
#pragma unroll
      for (int bb = 0; bb < 4; bb++){
        int b = bown + bb;
        float4 og = xch[(b*2 + (1 - half))*32 + lane];
        float i0,i1,f0v,f1v,g0v,g1v,o0v,o1v;
        if (half == 0){
          i0 = gf[b][0]; i1 = gf[b][1]; f0v = gf[b][2]; f1v = gf[b][3];
          g0v = og.x; g1v = og.y; o0v = og.z; o1v = og.w;
        } else {
          g0v = gf[b][0]; g1v = gf[b][1]; o0v = gf[b][2]; o1v = gf[b][3];
          i0 = og.x; i1 = og.y; f0v = og.z; f1v = og.w;
        }
        float c0 = sigf(f0v)*cx0[bb] + sigf(i0)*tanhf_fast(g0v);
        float c1 = sigf(f1v)*cx1[bb] + sigf(i1)*tanhf_fast(g1v);
        cx0[bb] = c0; cx1[bb] = c1;
        float h0 = sigf(o0v)*tanhf_fast(c0);
        float h1 = sigf(o1v)*tanhf_fast(c1);
        hxs[b*HID + lane]      = h0;
        hxs[b*HID + lane + 32] = h1;
#pragma unroll
        for (int ch = 0; ch < 3; ch++)
          p[bb][ch] = h0*wl0[ch] + h1*wl1[ch];
      }

      // butterfly-reduce the 12 head dot-products
#pragma unroll
      for (int off = 16; off >= 1; off >>= 1)
#pragma unroll
        for (int bb = 0; bb < 4; bb++)
#pragma unroll
          for (int ch = 0; ch < 3; ch++)
            p[bb][ch] += __shfl_xor_sync(FULLMASK, p[bb][ch], off);

      // leaky-relu, write v into row buffer quads + output
#pragma unroll
      for (int bb = 0; bb < 4; bb++)
#pragma unroll
        for (int ch = 0; ch < 3; ch++){
          float v = p[bb][ch] + blv[ch];
          v = (v >= 0.f) ? v : 0.01f*v;
          if (lane == bb*3 + ch){
            int b = bown + bb;
#pragma unroll
            for (int t = 0; t < 4; t++){
              int base = c - t;
              rbf[((b*3 + ch)*WIDTH + base)*4 + t] = v;
            }
            out[((size_t)(bpair + b)*3 + ch)*(OW*OW)
                + (r - L0R)*OW + (c - RS)] = v;
          }
        }
      PBAR();
    }
  }
}

extern "C" void kernel_launch(void* const* d_in, const int* in_sizes, int n_in,
                              void* d_out, int out_size)
{
  const float* x    = (const float*)d_in[0];
  const float* W_ih = (const float*)d_in[1];
  const float* W_hh = (const float*)d_in[2];
  const float* b_ih = (const float*)d_in[3];
  const float* b_hh = (const float*)d_in[4];
  const float* Wl   = (const float*)d_in[5];
  const float* bl   = (const float*)d_in[6];

  int B = in_sizes[0] / (3*WIDTH*WIDTH);
  int grid = B / CTAB;   // 4096/32 = 128 CTAs

  size_t smem = SMEM_FLOATS * sizeof(float);   // ~166 KB
  cudaFuncSetAttribute(pixelrnn_kernel,
                       cudaFuncAttributeMaxDynamicSharedMemorySize, (int)smem);

  pixelrnn_kernel<<<grid, NTHR, smem>>>(x, W_ih, W_hh, b_ih, b_hh, Wl, bl,
                                        (float*)d_out);
}